// round 17
// baseline (speedup 1.0000x reference)
#include <cuda_runtime.h>
#include <cuda_fp16.h>
#include <math.h>
#include <stdint.h>

#define BB 4
#define NN 4096
#define DD 128
#define KSPLIT 8                 // pv split-K factor
#define CHUNKS_PER_SPLIT 8       // 8 chunks of 64 halves = 512 per split

// ---------------- scratch (device globals; allocation-free) ----------------
__device__ __half g_Eh[(size_t)BB * NN * NN];  // exp(S), fp16 (134 MB)
__device__ float g_l[BB * NN];                 // column sums over q (of fp16-rounded E)
__device__ __half g_Qh[(size_t)BB * NN * DD];  // fp16 Q
__device__ __half g_Kh[(size_t)BB * NN * DD];  // fp16 K
__device__ __half g_VTh[(size_t)BB * DD * NN]; // V^T scaled by 1/l, fp16
__device__ __half g_Poh[(size_t)KSPLIT * BB * NN * DD];  // pv split partials (fp16)

// ---------------- helpers ----------------
__device__ __forceinline__ uint32_t smem_u32(const void* p) {
    uint32_t a;
    asm("{ .reg .u64 t; cvta.to.shared.u64 t, %1; cvt.u32.u64 %0, t; }" : "=r"(a) : "l"(p));
    return a;
}

#define CP_ASYNC16(s, g) asm volatile("cp.async.cg.shared.global [%0], [%1], 16;" :: "r"(s), "l"(g))
#define CP_COMMIT()      asm volatile("cp.async.commit_group;" ::: "memory")
#define CP_WAIT(n)       asm volatile("cp.async.wait_group %0;" :: "n"(n) : "memory")

// m16n8k16 fp16 MMA, fp32 accumulate
__device__ __forceinline__ void mma_f16(float* c, const uint32_t* a, const uint32_t* b) {
    asm volatile(
        "mma.sync.aligned.m16n8k16.row.col.f32.f16.f16.f32 "
        "{%0,%1,%2,%3}, {%4,%5,%6,%7}, {%8,%9}, {%0,%1,%2,%3};"
        : "+f"(c[0]), "+f"(c[1]), "+f"(c[2]), "+f"(c[3])
        : "r"(a[0]), "r"(a[1]), "r"(a[2]), "r"(a[3]), "r"(b[0]), "r"(b[1]));
}

__device__ __forceinline__ void ldsm_x4(uint32_t* r, uint32_t addr) {
    asm volatile("ldmatrix.sync.aligned.m8n8.x4.shared.b16 {%0,%1,%2,%3}, [%4];"
                 : "=r"(r[0]), "=r"(r[1]), "=r"(r[2]), "=r"(r[3]) : "r"(addr));
}
__device__ __forceinline__ void ldsm_x2(uint32_t* r, uint32_t addr) {
    asm volatile("ldmatrix.sync.aligned.m8n8.x2.shared.b16 {%0,%1}, [%2];"
                 : "=r"(r[0]), "=r"(r[1]) : "r"(addr));
}

// ---------------- small kernels ----------------
__global__ void cvt_kernel(const float* __restrict__ Q, const float* __restrict__ K) {
    size_t n = (size_t)BB * NN * DD;
    size_t i = (size_t)blockIdx.x * blockDim.x + threadIdx.x;
    if (i < n) {
        g_Qh[i] = __float2half_rn(Q[i]);
        g_Kh[i] = __float2half_rn(K[i]);
    }
    if (i < BB * NN) g_l[i] = 0.0f;
}
// VT[b][d][k] = fp16(V[b][k][d] / l[b][k])  — one batch per launch
__global__ void vt_kernel(const float* __restrict__ V, int b) {
    __shared__ float ts[32][33];
    int d0 = blockIdx.y * 32, k0 = blockIdx.x * 32;
    int tx = threadIdx.x, ty = threadIdx.y;
    const float* Vb = V + (size_t)b * NN * DD;
#pragma unroll
    for (int i = 0; i < 4; i++) {
        int r = ty + i * 8;
        ts[r][tx] = Vb[(size_t)(k0 + r) * DD + d0 + tx];
    }
    __syncthreads();
    float linv = 1.0f / g_l[b * NN + k0 + tx];
#pragma unroll
    for (int i = 0; i < 4; i++) {
        int d = ty + i * 8;
        g_VTh[((size_t)b * DD + d0 + d) * NN + k0 + tx] = __float2half_rn(ts[tx][d] * linv);
    }
}
// O = sum of KSPLIT fp16 partials (deterministic order), 8 elems per thread
__global__ void reduce_kernel(float* __restrict__ O) {
    size_t i = ((size_t)blockIdx.x * blockDim.x + threadIdx.x) * 8;
    const size_t stride = (size_t)BB * NN * DD;
    if (i < stride) {
        float s[8];
#pragma unroll
        for (int t = 0; t < 8; t++) s[t] = 0.0f;
#pragma unroll
        for (int p = 0; p < KSPLIT; p++) {
            uint4 v = *(const uint4*)(g_Poh + (size_t)p * stride + i);
            const __half2* h = (const __half2*)&v;
#pragma unroll
            for (int t = 0; t < 4; t++) {
                float2 f = __half22float2(h[t]);
                s[t * 2 + 0] += f.x;
                s[t * 2 + 1] += f.y;
            }
        }
        *(float4*)(O + i)     = make_float4(s[0], s[1], s[2], s[3]);
        *(float4*)(O + i + 4) = make_float4(s[4], s[5], s[6], s[7]);
    }
}

// ---------------- kernel 1: E(b) = exp(QK^T/sqrt(D)) fp16, l = colsum(E) ----------------
// grid (32 kt, 32 qt), one batch per launch; 256 threads (8 warps, 2x4), tile 128x128.
// Monolithic tiles (272B row stride), one wait + one barrier, 8 k16 MMA steps.
#define QK_TILE (128 * 272)   // 34816
#define SM1 (2 * QK_TILE)     // 69632
__global__ __launch_bounds__(256, 2) void qk_exp_kernel(int b) {
    const int qb = blockIdx.y * 128, kb = blockIdx.x * 128;
    const int tid = threadIdx.x, lane = tid & 31, wid = tid >> 5;
    const int wm = wid >> 2, wn = wid & 3;

    extern __shared__ __align__(16) char dyn[];
    uint32_t sbase = smem_u32(dyn);
    const uint32_t sA = sbase, sB = sbase + QK_TILE;

    const __half* Qg = g_Qh + ((size_t)b * NN + qb) * DD;
    const __half* Kg = g_Kh + ((size_t)b * NN + kb) * DD;

#pragma unroll
    for (int i = 0; i < 8; i++) {
        int idx = i * 256 + tid;
        int row = idx >> 4, c4 = idx & 15;
        CP_ASYNC16(sA + row * 272 + c4 * 16, Qg + (size_t)row * DD + c4 * 8);
    }
#pragma unroll
    for (int i = 0; i < 8; i++) {
        int idx = i * 256 + tid;
        int row = idx >> 4, c4 = idx & 15;
        CP_ASYNC16(sB + row * 272 + c4 * 16, Kg + (size_t)row * DD + c4 * 8);
    }
    CP_COMMIT();

    uint32_t a_off[4], b_off[4];
#pragma unroll
    for (int i = 0; i < 4; i++)
        a_off[i] = (uint32_t)(wm * 64 + i * 16 + (lane & 15)) * 272 + (uint32_t)(lane >> 4) * 16;
#pragma unroll
    for (int j = 0; j < 4; j++)
        b_off[j] = (uint32_t)(wn * 32 + j * 8 + (lane & 7)) * 272 + (uint32_t)((lane >> 3) & 1) * 16;

    float acc[4][4][4];
#pragma unroll
    for (int i = 0; i < 4; i++)
#pragma unroll
        for (int j = 0; j < 4; j++)
#pragma unroll
            for (int t = 0; t < 4; t++) acc[i][j][t] = 0.0f;

    CP_WAIT(0);
    __syncthreads();

#pragma unroll
    for (int ks = 0; ks < 8; ks++) {
        const uint32_t k0b = ks * 32;
        uint32_t af[4][4], bf[4][2];
#pragma unroll
        for (int i = 0; i < 4; i++) ldsm_x4(af[i], sA + a_off[i] + k0b);
#pragma unroll
        for (int j = 0; j < 4; j++) ldsm_x2(bf[j], sB + b_off[j] + k0b);
#pragma unroll
        for (int i = 0; i < 4; i++)
#pragma unroll
            for (int j = 0; j < 4; j++) mma_f16(acc[i][j], af[i], bf[j]);
    }

    // ---- epilogue: exp -> fp16 -> SMEM stage -> coalesced global stores ----
    const float SCALE = 0.08838834764831845f;
    float csum[4][2];
#pragma unroll
    for (int j = 0; j < 4; j++) { csum[j][0] = 0.0f; csum[j][1] = 0.0f; }

    __syncthreads();  // everyone done reading tiles; reuse smem as 128x272B stage
#pragma unroll
    for (int i = 0; i < 4; i++) {
        const int row0 = wm * 64 + i * 16 + (lane >> 2);
#pragma unroll
        for (int j = 0; j < 4; j++) {
            __half h0 = __float2half_rn(__expf(acc[i][j][0] * SCALE));
            __half h1 = __float2half_rn(__expf(acc[i][j][1] * SCALE));
            __half h2 = __float2half_rn(__expf(acc[i][j][2] * SCALE));
            __half h3 = __float2half_rn(__expf(acc[i][j][3] * SCALE));
            const int col = wn * 32 + j * 8 + (lane & 3) * 2;
            *(__half2*)(dyn + row0 * 272 + col * 2)       = __halves2half2(h0, h1);
            *(__half2*)(dyn + (row0 + 8) * 272 + col * 2) = __halves2half2(h2, h3);
            csum[j][0] += __half2float(h0) + __half2float(h2);
            csum[j][1] += __half2float(h1) + __half2float(h3);
        }
    }
    __syncthreads();

#pragma unroll
    for (int it = 0; it < 8; it++) {
        const int row = it * 16 + (tid >> 4);
        const int ch = tid & 15;
        uint4 v = *(const uint4*)(dyn + row * 272 + ch * 16);
        *(uint4*)(g_Eh + ((size_t)b * NN + qb + row) * NN + kb + ch * 8) = v;
    }

#pragma unroll
    for (int j = 0; j < 4; j++) {
#pragma unroll
        for (int p = 0; p < 2; p++) {
            float v = csum[j][p];
            v += __shfl_xor_sync(0xffffffffu, v, 4);
            v += __shfl_xor_sync(0xffffffffu, v, 8);
            v += __shfl_xor_sync(0xffffffffu, v, 16);
            if (lane < 4)
                atomicAdd(&g_l[b * NN + kb + wn * 32 + j * 8 + lane * 2 + p], v);
        }
    }
}

// ---------------- kernel 2: partial O(b) = E_norm @ V (fp16 MMA, fp16 partials) ----------------
// grid (64 qt, KSPLIT), one batch per launch; 128 threads (4 warps), tile 64q x 128d,
// warp 64x32, 8 chunks of 64 k-halves (144B rows), 2-stage, single sync/iter, occ 4.
#define TILEA_H (64 * 144)    // 9216
#define TILEB_H (128 * 144)   // 18432
#define SM2 (2 * (TILEA_H + TILEB_H))  // 55296
__device__ __forceinline__ void pv_loadA(uint32_t sdst, const __half* g, int tid) {
#pragma unroll
    for (int i = 0; i < 4; i++) {
        int idx = i * 128 + tid;
        int row = idx >> 3, c4 = idx & 7;
        CP_ASYNC16(sdst + row * 144 + c4 * 16, g + (size_t)row * NN + c4 * 8);
    }
}
__device__ __forceinline__ void pv_loadB(uint32_t sdst, const __half* g, int tid) {
#pragma unroll
    for (int i = 0; i < 8; i++) {
        int idx = i * 128 + tid;
        int row = idx >> 3, c4 = idx & 7;
        CP_ASYNC16(sdst + row * 144 + c4 * 16, g + (size_t)row * NN + c4 * 8);
    }
}
__global__ __launch_bounds__(128, 4) void pv_kernel(int b) {
    const int split = blockIdx.y, qb = blockIdx.x * 64;
    const int tid = threadIdx.x, lane = tid & 31, wn = tid >> 5;
    const int c0 = split * CHUNKS_PER_SPLIT;

    extern __shared__ __align__(16) char dyn[];
    uint32_t sbase = smem_u32(dyn);
    uint32_t sA[2] = { sbase, sbase + TILEA_H };
    uint32_t sB[2] = { sbase + 2 * TILEA_H, sbase + 2 * TILEA_H + TILEB_H };

    const __half* Eg = g_Eh + ((size_t)b * NN + qb) * NN;
    const __half* Vg = g_VTh + (size_t)b * DD * NN;

    uint32_t a_off[4], b_off[4];
#pragma unroll
    for (int i = 0; i < 4; i++)
        a_off[i] = (uint32_t)(i * 16 + (lane & 15)) * 144 + (uint32_t)(lane >> 4) * 16;
#pragma unroll
    for (int j = 0; j < 4; j++)
        b_off[j] = (uint32_t)(wn * 32 + j * 8 + (lane & 7)) * 144 + (uint32_t)((lane >> 3) & 1) * 16;

    float acc[4][4][4];
#pragma unroll
    for (int i = 0; i < 4; i++)
#pragma unroll
        for (int j = 0; j < 4; j++)
#pragma unroll
            for (int t = 0; t < 4; t++) acc[i][j][t] = 0.0f;

    pv_loadA(sA[0], Eg + (size_t)c0 * 64, tid);
    pv_loadB(sB[0], Vg + (size_t)c0 * 64, tid);
    CP_COMMIT();

#pragma unroll 1
    for (int c = 0; c < CHUNKS_PER_SPLIT; c++) {
        CP_WAIT(0);
        __syncthreads();
        if (c + 1 < CHUNKS_PER_SPLIT) {
            pv_loadA(sA[(c + 1) & 1], Eg + (size_t)(c0 + c + 1) * 64, tid);
            pv_loadB(sB[(c + 1) & 1], Vg + (size_t)(c0 + c + 1) * 64, tid);
            CP_COMMIT();
        }
        const uint32_t Ab = sA[c & 1], Bb = sB[c & 1];
#pragma unroll
        for (int ks = 0; ks < 4; ks++) {
            const uint32_t k0b = ks * 32;
            uint32_t af[4][4], bf[4][2];
#pragma unroll
            for (int i = 0; i < 4; i++) ldsm_x4(af[i], Ab + a_off[i] + k0b);
#pragma unroll
            for (int j = 0; j < 4; j++) ldsm_x2(bf[j], Bb + b_off[j] + k0b);
#pragma unroll
            for (int i = 0; i < 4; i++)
#pragma unroll
                for (int j = 0; j < 4; j++) mma_f16(acc[i][j], af[i], bf[j]);
        }
    }

    __half* Po = g_Poh + (size_t)split * BB * NN * DD;
#pragma unroll
    for (int i = 0; i < 4; i++) {
        const int row0 = qb + i * 16 + (lane >> 2);
#pragma unroll
        for (int j = 0; j < 4; j++) {
            const int col = wn * 32 + j * 8 + (lane & 3) * 2;
            *(__half2*)(Po + ((size_t)b * NN + row0) * DD + col) =
                __floats2half2_rn(acc[i][j][0], acc[i][j][1]);
            *(__half2*)(Po + ((size_t)b * NN + row0 + 8) * DD + col) =
                __floats2half2_rn(acc[i][j][2], acc[i][j][3]);
        }
    }
}

// ---------------- launch: per-batch chaining keeps E(b) (33.5 MB) L2-resident ----------------
extern "C" void kernel_launch(void* const* d_in, const int* in_sizes, int n_in,
                              void* d_out, int out_size) {
    const float* q = (const float*)d_in[0];
    const float* k = (const float*)d_in[1];
    const float* v = (const float*)d_in[2];
    float* out = (float*)d_out;

    cudaFuncSetAttribute(qk_exp_kernel, cudaFuncAttributeMaxDynamicSharedMemorySize, SM1);
    cudaFuncSetAttribute(pv_kernel, cudaFuncAttributeMaxDynamicSharedMemorySize, SM2);

    size_t nqk = (size_t)BB * NN * DD;
    cvt_kernel<<<(unsigned)((nqk + 255) / 256), 256>>>(q, k);

    for (int b = 0; b < BB; b++) {
        qk_exp_kernel<<<dim3(NN / 128, NN / 128), 256, SM1>>>(b);
        vt_kernel<<<dim3(NN / 32, DD / 32), dim3(32, 8)>>>(v, b);
        pv_kernel<<<dim3(NN / 64, KSPLIT), 128, SM2>>>(b);
    }

    size_t nout = (size_t)BB * NN * DD;
    reduce_kernel<<<(unsigned)((nout / 8 + 255) / 256), 256>>>(out);
}